// round 5
// baseline (speedup 1.0000x reference)
#include <cuda_runtime.h>
#include <cuda_bf16.h>

// Problem constants: N=4096 atoms, M=64 neighbors, Q=64, H=64, T=4 types
#define NATOMS 4096
#define MNBR   64
#define QD     64
#define HD     64

#define DE_BLOCKS 1024          // de-role: 4 atoms per block, 256 thr
#define W_BLOCKS  512           // w-role: 512 (i,m) pairs per block, 256 thr
#define APB       4             // atoms per stream block
#define SBLOCKS   (NATOMS / APB) // 1024 stream blocks

// Scratch (rewritten fully every launch -> deterministic).
__device__ float        g_de[NATOMS * QD];     // de_dq per atom
__device__ float        g_w[NATOMS * MNBR];    // -r2 weight per (i,m)
__device__ float        g_partials[3 * SBLOCKS];
__device__ unsigned int g_ticket = 0u;         // reset by last stream block

// ---------------------------------------------------------------------------
// Prep: role-split. Blocks [0,1024): de_dq. Blocks [1024,1536): w = -r2.
// ---------------------------------------------------------------------------
__global__ __launch_bounds__(256) void tnep_prep(
    const float* __restrict__ desc,     // [N, Q]
    const float* __restrict__ pos,      // [N, 3]
    const float* __restrict__ box,      // [3, 3]
    const float* __restrict__ W0,       // [T, Q, H]
    const float* __restrict__ b0,       // [T, H]
    const float* __restrict__ W1,       // [T, H]
    const int*   __restrict__ Z,        // [N]
    const int*   __restrict__ gidx)     // [N, M]
{
    const int tid = threadIdx.x;

    if (blockIdx.x < DE_BLOCKS) {
        // ---- de role: thread = (local atom a, output index x) ----
        __shared__ float gj_s[APB * HD];
        const int a = tid >> 6;
        const int x = tid & 63;
        const int i = blockIdx.x * 4 + a;
        const int z = Z[i];
        const float* __restrict__ W0z = W0 + (size_t)z * QD * HD;
        const float* __restrict__ di  = desc + (size_t)i * QD;

        // step A: hidden j = x; column access (coalesced across x, L1-resident)
        float s = b0[z * HD + x];
        #pragma unroll
        for (int q = 0; q < QD; q++) s += di[q] * W0z[q * HD + x];
        const float h = tanhf(s);
        gj_s[a * HD + x] = (1.0f - h * h) * W1[z * HD + x];
        __syncthreads();

        // step B: q = x; row access per thread (256B row from L1)
        float t = 0.0f;
        #pragma unroll
        for (int j = 0; j < HD; j++) t += gj_s[a * HD + j] * W0z[x * HD + j];
        g_de[(size_t)i * QD + x] = t;
    } else {
        // ---- w role: 512 consecutive (i,m) pairs per block ----
        const int bid = blockIdx.x - DE_BLOCKS;
        const float b00 = box[0], b01 = box[1], b02 = box[2];
        const float b10 = box[3], b11 = box[4], b12 = box[5];
        const float b20 = box[6], b21 = box[7], b22 = box[8];
        const float det = b00 * (b11 * b22 - b12 * b21)
                        - b01 * (b10 * b22 - b12 * b20)
                        + b02 * (b10 * b21 - b11 * b20);
        const float rd = 1.0f / det;
        const float i00 = (b11 * b22 - b12 * b21) * rd, i01 = (b02 * b21 - b01 * b22) * rd, i02 = (b01 * b12 - b02 * b11) * rd;
        const float i10 = (b12 * b20 - b10 * b22) * rd, i11 = (b00 * b22 - b02 * b20) * rd, i12 = (b02 * b10 - b00 * b12) * rd;
        const float i20 = (b10 * b21 - b11 * b20) * rd, i21 = (b01 * b20 - b00 * b21) * rd, i22 = (b00 * b11 - b01 * b10) * rd;

        #pragma unroll
        for (int r = 0; r < 2; r++) {
            const int p = bid * 512 + r * 256 + tid;   // pair index
            const int i = p >> 6;
            const int j = gidx[p];
            const float dx = pos[j * 3 + 0] - pos[i * 3 + 0];
            const float dy = pos[j * 3 + 1] - pos[i * 3 + 1];
            const float dz = pos[j * 3 + 2] - pos[i * 3 + 2];
            float s0 = dx * i00 + dy * i10 + dz * i20;
            float s1 = dx * i01 + dy * i11 + dz * i21;
            float s2 = dx * i02 + dy * i12 + dz * i22;
            s0 -= rintf(s0); s1 -= rintf(s1); s2 -= rintf(s2);  // jnp.round
            const float e0 = s0 * b00 + s1 * b10 + s2 * b20;
            const float e1 = s0 * b01 + s1 * b11 + s2 * b21;
            const float e2 = s0 * b02 + s1 * b12 + s2 * b22;
            float r2 = e0 * e0 + e1 * e1 + e2 * e2;
            if (j == i) r2 = 0.0f;       // diagonal mask
            g_w[p] = -r2;                // dipole minus sign folded in
        }
    }
}

// ---------------------------------------------------------------------------
// Stream: 1024 blocks x 192 thr, 4 atoms each. One barrier in the hot path;
// 8-deep rolling load window flowing across atom boundaries. Scalar carry
// per thread (fixed channel) -> one reduce + one ticket per block.
// ---------------------------------------------------------------------------
__global__ __launch_bounds__(192) void tnep_stream(
    const float* __restrict__ grads,    // [N, M, 3, Q]
    float*       __restrict__ out)      // [3]
{
    __shared__ float de_s[APB * QD];
    __shared__ float w_s[APB * MNBR];
    __shared__ float sval[12];
    __shared__ float wsum[6];
    __shared__ int   is_last_s;

    const int tid   = threadIdx.x;
    const int atom0 = blockIdx.x * APB;

    // --- issue first 8 grad loads immediately ---
    const float4* __restrict__ g4 =
        reinterpret_cast<const float4*>(grads) + (size_t)atom0 * 3072;
    float4 buf[8];
    #pragma unroll
    for (int k = 0; k < 8; k++) buf[k] = g4[k * 192 + tid];

    // --- overlapped: stage this block's de and w slices (coalesced) ---
    #pragma unroll
    for (int idx = tid; idx < APB * 64; idx += 192) {
        de_s[idx] = g_de[(size_t)atom0 * QD + idx];
        w_s[idx]  = g_w[(size_t)atom0 * MNBR + idx];
    }
    __syncthreads();   // the only hot-path barrier

    const int e4    = tid % 48;
    const int m_off = tid / 48;
    const int q4    = e4 & 15;
    float carry = 0.0f;
    float4 acc = make_float4(0.f, 0.f, 0.f, 0.f);

    #pragma unroll
    for (int a = 0; a < APB; a++) {
        #pragma unroll
        for (int k = 0; k < 16; k++) {
            const int it = a * 16 + k;
            const float4 g = buf[it & 7];
            if (it + 8 < APB * 16)     // compile-time after full unroll
                buf[it & 7] = g4[((it + 8) >> 4) * 3072 + ((it + 8) & 15) * 192 + tid];
            const float w = w_s[a * 64 + k * 4 + m_off];
            acc.x += w * g.x; acc.y += w * g.y; acc.z += w * g.z; acc.w += w * g.w;
        }
        carry += acc.x * de_s[a * 64 + q4 * 4 + 0]
               + acc.y * de_s[a * 64 + q4 * 4 + 1]
               + acc.z * de_s[a * 64 + q4 * 4 + 2]
               + acc.w * de_s[a * 64 + q4 * 4 + 3];
        acc = make_float4(0.f, 0.f, 0.f, 0.f);
    }

    // --- once per block: reduce over aligned 16-lane groups (uniform channel) ---
    #pragma unroll
    for (int off = 8; off >= 1; off >>= 1)
        carry += __shfl_down_sync(0xffffffffu, carry, off, 16);
    const int lane = tid & 31;
    const int warp = tid >> 5;
    if ((lane & 15) == 0) sval[warp * 2 + (lane >> 4)] = carry;  // group g -> channel g%3
    __syncthreads();

    if (tid == 0) {
        float p0 = 0.f, p1 = 0.f, p2 = 0.f;
        #pragma unroll
        for (int g = 0; g < 12; g += 3) {
            p0 += sval[g + 0];
            p1 += sval[g + 1];
            p2 += sval[g + 2];
        }
        g_partials[0 * SBLOCKS + blockIdx.x] = p0;
        g_partials[1 * SBLOCKS + blockIdx.x] = p1;
        g_partials[2 * SBLOCKS + blockIdx.x] = p2;
        __threadfence();
        const unsigned int t = atomicAdd(&g_ticket, 1u);
        is_last_s = (t == (unsigned)(gridDim.x - 1)) ? 1 : 0;
    }
    __syncthreads();

    // --- last block: fixed-order final reduction over 3 x 1024 partials ---
    if (is_last_s) {
        __threadfence();
        const int c  = tid >> 6;          // 0..2 (warps channel-uniform)
        const int j0 = tid & 63;
        const float* pc = g_partials + c * SBLOCKS;
        float a = 0.f;
        #pragma unroll 4
        for (int j = j0; j < SBLOCKS; j += 64) a += pc[j];
        #pragma unroll
        for (int off = 16; off >= 1; off >>= 1)
            a += __shfl_down_sync(0xffffffffu, a, off);
        if ((tid & 31) == 0) wsum[tid >> 5] = a;
        __syncthreads();
        if (tid < 3) out[tid] = wsum[2 * tid] + wsum[2 * tid + 1];
        if (tid == 0) g_ticket = 0u;      // reset for next graph replay
    }
}

extern "C" void kernel_launch(void* const* d_in, const int* in_sizes, int n_in,
                              void* d_out, int out_size) {
    const float* descriptors = (const float*)d_in[0];   // [4096, 64]
    const float* gradients   = (const float*)d_in[1];   // [4096, 64, 3, 64]
    const float* positions   = (const float*)d_in[2];   // [4096, 3]
    const float* box         = (const float*)d_in[3];   // [3, 3]
    const float* W0          = (const float*)d_in[4];   // [4, 64, 64]
    const float* b0          = (const float*)d_in[5];   // [4, 64]
    const float* W1          = (const float*)d_in[6];   // [4, 64]
    const int*   Z           = (const int*)d_in[7];     // [4096]
    const int*   grad_index  = (const int*)d_in[8];     // [4096, 64]
    float* out = (float*)d_out;                         // [3]

    tnep_prep<<<DE_BLOCKS + W_BLOCKS, 256>>>(descriptors, positions, box,
                                             W0, b0, W1, Z, grad_index);
    tnep_stream<<<SBLOCKS, 192>>>(gradients, out);
}

// round 6
// speedup vs baseline: 1.9785x; 1.9785x over previous
#include <cuda_runtime.h>
#include <cuda_bf16.h>

// Problem constants: N=4096 atoms, M=64 neighbors, Q=64, H=64, T=4 types
#define NATOMS 4096
#define MNBR   64
#define QD     64
#define HD     64
#define NTYPES 4

#define DE_BLOCKS 1024           // de-role: 4 atoms per block, 256 thr
#define W_BLOCKS  512            // w-role: 512 (i,m) pairs per block, 256 thr
#define APB       4              // atoms per stream block
#define SBLOCKS   (NATOMS / APB) // 1024 stream blocks

// Scratch (rewritten fully every launch -> deterministic).
__device__ float        g_W0T[NTYPES * HD * QD]; // W0 transposed: [T][j][q]
__device__ float        g_de[NATOMS * QD];       // de_dq per atom
__device__ float        g_w[NATOMS * MNBR];      // -r2 weight per (i,m)
__device__ float        g_partials[3 * SBLOCKS];
__device__ unsigned int g_ticket = 0u;           // reset by last stream block

// ---------------------------------------------------------------------------
// Kernel 0: transpose W0 per type (4 blocks, 256 thr). 64 KiB total.
// ---------------------------------------------------------------------------
__global__ __launch_bounds__(256) void tnep_transpose(
    const float* __restrict__ W0)       // [T, Q, H]
{
    __shared__ float s[QD][HD + 1];     // padded: conflict-free transposed read
    const int t   = blockIdx.x;
    const int tid = threadIdx.x;
    const float* __restrict__ src = W0 + (size_t)t * QD * HD;

    #pragma unroll
    for (int it = 0; it < 16; it++) {
        const int idx = it * 256 + tid;             // 0..4095
        s[idx >> 6][idx & 63] = src[idx];           // coalesced read
    }
    __syncthreads();
    #pragma unroll
    for (int it = 0; it < 16; it++) {
        const int idx = it * 256 + tid;             // out idx = j*64 + q
        g_W0T[(size_t)t * QD * HD + idx] = s[idx & 63][idx >> 6];  // coalesced write
    }
}

// ---------------------------------------------------------------------------
// Kernel 1: role-split prep. Blocks [0,1024): de_dq (both steps coalesced).
// Blocks [1024,1536): w = -r2.
// ---------------------------------------------------------------------------
__global__ __launch_bounds__(256) void tnep_prep(
    const float* __restrict__ desc,     // [N, Q]
    const float* __restrict__ pos,      // [N, 3]
    const float* __restrict__ box,      // [3, 3]
    const float* __restrict__ W0,       // [T, Q, H]
    const float* __restrict__ b0,       // [T, H]
    const float* __restrict__ W1,       // [T, H]
    const int*   __restrict__ Z,        // [N]
    const int*   __restrict__ gidx)     // [N, M]
{
    const int tid = threadIdx.x;

    if (blockIdx.x < DE_BLOCKS) {
        // ---- de role: thread = (local atom a, output index x) ----
        __shared__ float gj_s[4 * HD];
        const int a = tid >> 6;
        const int x = tid & 63;
        const int i = blockIdx.x * 4 + a;
        const int z = Z[i];
        const float* __restrict__ W0z  = W0    + (size_t)z * QD * HD;
        const float* __restrict__ W0Tz = g_W0T + (size_t)z * QD * HD;
        const float* __restrict__ di   = desc  + (size_t)i * QD;

        // step A (coalesced across x): hidden j = x
        float s = b0[z * HD + x];
        #pragma unroll
        for (int q = 0; q < QD; q++) s += di[q] * W0z[q * HD + x];
        const float h = tanhf(s);
        gj_s[a * HD + x] = (1.0f - h * h) * W1[z * HD + x];
        __syncthreads();

        // step B (coalesced across x via transpose): de[q = x]
        float t = 0.0f;
        #pragma unroll
        for (int j = 0; j < HD; j++) t += gj_s[a * HD + j] * W0Tz[j * QD + x];
        g_de[(size_t)i * QD + x] = t;
    } else {
        // ---- w role: 512 consecutive (i,m) pairs per block ----
        const int bid = blockIdx.x - DE_BLOCKS;
        const float b00 = box[0], b01 = box[1], b02 = box[2];
        const float b10 = box[3], b11 = box[4], b12 = box[5];
        const float b20 = box[6], b21 = box[7], b22 = box[8];
        const float det = b00 * (b11 * b22 - b12 * b21)
                        - b01 * (b10 * b22 - b12 * b20)
                        + b02 * (b10 * b21 - b11 * b20);
        const float rd = 1.0f / det;
        const float i00 = (b11 * b22 - b12 * b21) * rd, i01 = (b02 * b21 - b01 * b22) * rd, i02 = (b01 * b12 - b02 * b11) * rd;
        const float i10 = (b12 * b20 - b10 * b22) * rd, i11 = (b00 * b22 - b02 * b20) * rd, i12 = (b02 * b10 - b00 * b12) * rd;
        const float i20 = (b10 * b21 - b11 * b20) * rd, i21 = (b01 * b20 - b00 * b21) * rd, i22 = (b00 * b11 - b01 * b10) * rd;

        #pragma unroll
        for (int r = 0; r < 2; r++) {
            const int p = bid * 512 + r * 256 + tid;   // pair index
            const int i = p >> 6;
            const int j = gidx[p];
            const float dx = pos[j * 3 + 0] - pos[i * 3 + 0];
            const float dy = pos[j * 3 + 1] - pos[i * 3 + 1];
            const float dz = pos[j * 3 + 2] - pos[i * 3 + 2];
            float s0 = dx * i00 + dy * i10 + dz * i20;
            float s1 = dx * i01 + dy * i11 + dz * i21;
            float s2 = dx * i02 + dy * i12 + dz * i22;
            s0 -= rintf(s0); s1 -= rintf(s1); s2 -= rintf(s2);  // jnp.round
            const float e0 = s0 * b00 + s1 * b10 + s2 * b20;
            const float e1 = s0 * b01 + s1 * b11 + s2 * b21;
            const float e2 = s0 * b02 + s1 * b12 + s2 * b22;
            float r2 = e0 * e0 + e1 * e1 + e2 * e2;
            if (j == i) r2 = 0.0f;       // diagonal mask
            g_w[p] = -r2;                // dipole minus sign folded in
        }
    }
}

// ---------------------------------------------------------------------------
// Kernel 2: the bandwidth kernel (unchanged from round 5: 36.2us, DRAM 72.5%).
// 1024 blocks x 192 thr, 4 atoms each, one barrier, 8-deep rolling window.
// ---------------------------------------------------------------------------
__global__ __launch_bounds__(192) void tnep_stream(
    const float* __restrict__ grads,    // [N, M, 3, Q]
    float*       __restrict__ out)      // [3]
{
    __shared__ float de_s[APB * QD];
    __shared__ float w_s[APB * MNBR];
    __shared__ float sval[12];
    __shared__ float wsum[6];
    __shared__ int   is_last_s;

    const int tid   = threadIdx.x;
    const int atom0 = blockIdx.x * APB;

    // --- issue first 8 grad loads immediately ---
    const float4* __restrict__ g4 =
        reinterpret_cast<const float4*>(grads) + (size_t)atom0 * 3072;
    float4 buf[8];
    #pragma unroll
    for (int k = 0; k < 8; k++) buf[k] = g4[k * 192 + tid];

    // --- overlapped: stage this block's de and w slices (coalesced) ---
    #pragma unroll
    for (int idx = tid; idx < APB * 64; idx += 192) {
        de_s[idx] = g_de[(size_t)atom0 * QD + idx];
        w_s[idx]  = g_w[(size_t)atom0 * MNBR + idx];
    }
    __syncthreads();   // the only hot-path barrier

    const int e4    = tid % 48;
    const int m_off = tid / 48;
    const int q4    = e4 & 15;
    float carry = 0.0f;
    float4 acc = make_float4(0.f, 0.f, 0.f, 0.f);

    #pragma unroll
    for (int a = 0; a < APB; a++) {
        #pragma unroll
        for (int k = 0; k < 16; k++) {
            const int it = a * 16 + k;
            const float4 g = buf[it & 7];
            if (it + 8 < APB * 16)     // compile-time after full unroll
                buf[it & 7] = g4[((it + 8) >> 4) * 3072 + ((it + 8) & 15) * 192 + tid];
            const float w = w_s[a * 64 + k * 4 + m_off];
            acc.x += w * g.x; acc.y += w * g.y; acc.z += w * g.z; acc.w += w * g.w;
        }
        carry += acc.x * de_s[a * 64 + q4 * 4 + 0]
               + acc.y * de_s[a * 64 + q4 * 4 + 1]
               + acc.z * de_s[a * 64 + q4 * 4 + 2]
               + acc.w * de_s[a * 64 + q4 * 4 + 3];
        acc = make_float4(0.f, 0.f, 0.f, 0.f);
    }

    // --- once per block: reduce over aligned 16-lane groups (uniform channel) ---
    #pragma unroll
    for (int off = 8; off >= 1; off >>= 1)
        carry += __shfl_down_sync(0xffffffffu, carry, off, 16);
    const int lane = tid & 31;
    const int warp = tid >> 5;
    if ((lane & 15) == 0) sval[warp * 2 + (lane >> 4)] = carry;  // group g -> channel g%3
    __syncthreads();

    if (tid == 0) {
        float p0 = 0.f, p1 = 0.f, p2 = 0.f;
        #pragma unroll
        for (int g = 0; g < 12; g += 3) {
            p0 += sval[g + 0];
            p1 += sval[g + 1];
            p2 += sval[g + 2];
        }
        g_partials[0 * SBLOCKS + blockIdx.x] = p0;
        g_partials[1 * SBLOCKS + blockIdx.x] = p1;
        g_partials[2 * SBLOCKS + blockIdx.x] = p2;
        __threadfence();
        const unsigned int t = atomicAdd(&g_ticket, 1u);
        is_last_s = (t == (unsigned)(gridDim.x - 1)) ? 1 : 0;
    }
    __syncthreads();

    // --- last block: fixed-order final reduction over 3 x 1024 partials ---
    if (is_last_s) {
        __threadfence();
        const int c  = tid >> 6;          // 0..2 (warps channel-uniform)
        const int j0 = tid & 63;
        const float* pc = g_partials + c * SBLOCKS;
        float a = 0.f;
        #pragma unroll 4
        for (int j = j0; j < SBLOCKS; j += 64) a += pc[j];
        #pragma unroll
        for (int off = 16; off >= 1; off >>= 1)
            a += __shfl_down_sync(0xffffffffu, a, off);
        if ((tid & 31) == 0) wsum[tid >> 5] = a;
        __syncthreads();
        if (tid < 3) out[tid] = wsum[2 * tid] + wsum[2 * tid + 1];
        if (tid == 0) g_ticket = 0u;      // reset for next graph replay
    }
}

extern "C" void kernel_launch(void* const* d_in, const int* in_sizes, int n_in,
                              void* d_out, int out_size) {
    const float* descriptors = (const float*)d_in[0];   // [4096, 64]
    const float* gradients   = (const float*)d_in[1];   // [4096, 64, 3, 64]
    const float* positions   = (const float*)d_in[2];   // [4096, 3]
    const float* box         = (const float*)d_in[3];   // [3, 3]
    const float* W0          = (const float*)d_in[4];   // [4, 64, 64]
    const float* b0          = (const float*)d_in[5];   // [4, 64]
    const float* W1          = (const float*)d_in[6];   // [4, 64]
    const int*   Z           = (const int*)d_in[7];     // [4096]
    const int*   grad_index  = (const int*)d_in[8];     // [4096, 64]
    float* out = (float*)d_out;                         // [3]

    tnep_transpose<<<NTYPES, 256>>>(W0);
    tnep_prep<<<DE_BLOCKS + W_BLOCKS, 256>>>(descriptors, positions, box,
                                             W0, b0, W1, Z, grad_index);
    tnep_stream<<<SBLOCKS, 192>>>(gradients, out);
}